// round 10
// baseline (speedup 1.0000x reference)
#include <cuda_runtime.h>
#include <cuda_fp16.h>
#include <math.h>
#include <cstdint>

#define BB 8
#define LT 64
#define LV 16384
#define DD 256
#define EPSF 1e-6f

typedef unsigned int uint32;

#define PK 264   // padded row stride in fp16 elems (528B; 33 uint4 -> odd 16B-unit stride, conflict-free ldmatrix)

// smem byte offsets
#define SM_V    0                      // 128*264*2 = 67584
#define SM_T    67584                  // 64*264*2  = 33792
#define SM_RN   101376                 // 512
#define SM_RED  101888                 // 8*192*4 = 6144
#define SM_TOTAL 108032                // x2 CTAs = 216064 <= 227 KB

// ---------------- device globals ----------------
__device__ __half g_t16[BB*LT*DD];    // fp16 normalized t
__device__ float g_ES[(size_t)BB*LV*LT];
__device__ float g_den[BB*LT];
__device__ float g_num[BB*LT];
__device__ float g_zc[BB*LT];
__device__ float g_w[BB*LT];
__device__ unsigned g_mn[BB];
__device__ unsigned g_mx[BB];

__device__ __forceinline__ float fixf(float x) {
    if (isnan(x)) return 0.f;
    return fminf(fmaxf(x, -3.402823466e38f), 3.402823466e38f);
}
__device__ __forceinline__ uint32 smem_u32(const void* p) {
    uint32 a;
    asm("{ .reg .u64 t; cvta.to.shared.u64 t, %1; cvt.u32.u64 %0, t; }" : "=r"(a) : "l"(p));
    return a;
}
__device__ __forceinline__ uint32 packh2(float a, float b) {
    __half2 h = __floats2half2_rn(a, b);
    return *(uint32*)&h;
}

#define LDMX4(r, addr) \
    asm volatile("ldmatrix.sync.aligned.m8n8.x4.shared.b16 {%0,%1,%2,%3}, [%4];" \
        : "=r"((r)[0]), "=r"((r)[1]), "=r"((r)[2]), "=r"((r)[3]) : "r"(addr))

#define MMAH(c, a, b0, b1) \
    asm volatile("mma.sync.aligned.m16n8k16.row.col.f32.f16.f16.f32 " \
        "{%0,%1,%2,%3},{%4,%5,%6,%7},{%8,%9},{%0,%1,%2,%3};" \
        : "+f"((c)[0]), "+f"((c)[1]), "+f"((c)[2]), "+f"((c)[3]) \
        : "r"((a)[0]), "r"((a)[1]), "r"((a)[2]), "r"((a)[3]), "r"(b0), "r"(b1))

// ---------------- kernel 1: normalize t -> fp16; init accumulators ----------------
__global__ void k1_norm_t(const float* __restrict__ t) {
    int row = blockIdx.x;         // 0..511
    int tid = threadIdx.x;        // 0..255 = k
    if (row == 0) {
        for (int j = tid; j < BB*LT; j += 256) {
            g_den[j] = 0.f; g_num[j] = 0.f; g_zc[j] = 0.f;
        }
        if (tid < BB) { g_mn[tid] = 0x7F800000u; g_mx[tid] = 0u; }
    }
    float x = fixf(t[row*DD + tid]);
    float ss = x * x;
    #pragma unroll
    for (int o = 16; o >= 1; o >>= 1) ss += __shfl_xor_sync(0xffffffffu, ss, o);
    __shared__ float sh[8];
    if ((tid & 31) == 0) sh[tid >> 5] = ss;
    __syncthreads();
    float tot = 0.f;
    #pragma unroll
    for (int w = 0; w < 8; w++) tot += sh[w];
    float xn = x / fmaxf(sqrtf(tot), EPSF);
    g_t16[row*DD + tid] = __float2half_rn(xn);
}

// ---------------- kernel 2: single-pass fp16 HMMA S-GEMM + fused softmaxes ----------------
// Block: 128 v-rows x 64 t x K=256, single phase. 8 warps; warp w owns rows 16w..16w+15.
__global__ __launch_bounds__(256, 2) void k2_main(const float* __restrict__ v) {
    extern __shared__ char smc[];
    uint32 smb = smem_u32(smc);
    int b    = blockIdx.y;
    int row0 = blockIdx.x * 128;
    int tid  = threadIdx.x;
    int lane = tid & 31, w = tid >> 5;
    float* rn_s = (float*)(smc + SM_RN);
    float* red  = (float*)(smc + SM_RED);

    // ---- prologue: T fp16 tile into padded smem (2048 uint4) ----
    {
        const uint4* t4 = (const uint4*)(g_t16 + b*LT*DD);
        #pragma unroll
        for (int it = 0; it < 8; it++) {
            int i = tid + it*256;            // 0..2047
            int r = i >> 5, c = i & 31;      // 32 uint4 per 256-elem row
            *(uint4*)(smc + SM_T + (uint32)(r*PK + c*8)*2) = t4[i];
        }
    }
    // ---- prologue: V -> fp16 + row norms ----
    {
        int vrow = tid >> 1, khalf = (tid & 1) * 128;
        const float* vr = v + ((size_t)b*LV + row0 + vrow)*DD + khalf;
        float ss = 0.f;
        #pragma unroll 4
        for (int c = 0; c < 16; c++) {
            float4 p0 = *(const float4*)(vr + c*8);
            float4 p1 = *(const float4*)(vr + c*8 + 4);
            float x0=fixf(p0.x), x1=fixf(p0.y), x2=fixf(p0.z), x3=fixf(p0.w);
            float x4=fixf(p1.x), x5=fixf(p1.y), x6=fixf(p1.z), x7=fixf(p1.w);
            ss += x0*x0 + x1*x1 + x2*x2 + x3*x3 + x4*x4 + x5*x5 + x6*x6 + x7*x7;
            uint4 st = make_uint4(packh2(x0,x1), packh2(x2,x3), packh2(x4,x5), packh2(x6,x7));
            *(uint4*)(smc + SM_V + (uint32)(vrow*PK + khalf + c*8)*2) = st;
        }
        float st = ss + __shfl_xor_sync(0xffffffffu, ss, 1);
        if ((tid & 1) == 0) rn_s[vrow] = 0.5f / fmaxf(sqrtf(st), EPSF);
    }
    __syncthreads();

    // ---- mainloop: 16 k-steps, single fp16 pass ----
    float acc[8][4];
    #pragma unroll
    for (int nt = 0; nt < 8; nt++)
        #pragma unroll
        for (int j = 0; j < 4; j++) acc[nt][j] = 0.f;

    uint32 a_row = 16*w + (lane & 15);
    uint32 a_k8  = (lane >> 4) * 8;
    uint32 a_addr = smb + SM_V + (a_row*PK + a_k8) * 2;
    uint32 b_row = (lane & 7) + ((lane >> 4) << 3);
    uint32 b_k8  = ((lane >> 3) & 1) * 8;
    uint32 b_base = smb + SM_T + (b_row*PK + b_k8) * 2;

    #pragma unroll 4
    for (int ks = 0; ks < 16; ks++) {
        uint32 a[4];
        LDMX4(a, a_addr + ks*32);
        #pragma unroll
        for (int nc = 0; nc < 4; nc++) {
            uint32 bh[4];
            LDMX4(bh, b_base + (uint32)nc*(16*PK*2) + ks*32);
            MMAH(acc[2*nc],   a, bh[0], bh[1]);
            MMAH(acc[2*nc+1], a, bh[2], bh[3]);
        }
    }

    // ---- epilogue: shift-free softmax over t (|S|<=0.5), ES store, accumulators ----
    // c frag: row r1 = 16w + lane/4 -> c[0],c[1]; row r2 = r1+8 -> c[2],c[3];
    // col = nt*8 + (lane&3)*2 + e
    int r1 = 16*w + (lane >> 2);
    int r2 = r1 + 8;
    float sc1 = rn_s[r1], sc2 = rn_s[r2];

    // exp in place; z = row sums
    float z1 = 0.f, z2 = 0.f;
    #pragma unroll
    for (int nt = 0; nt < 8; nt++) {
        acc[nt][0] = __expf(acc[nt][0]*sc1); z1 += acc[nt][0];
        acc[nt][1] = __expf(acc[nt][1]*sc1); z1 += acc[nt][1];
        acc[nt][2] = __expf(acc[nt][2]*sc2); z2 += acc[nt][2];
        acc[nt][3] = __expf(acc[nt][3]*sc2); z2 += acc[nt][3];
    }
    #pragma unroll
    for (int o = 1; o < 4; o <<= 1) {
        z1 += __shfl_xor_sync(0xffffffffu, z1, o);
        z2 += __shfl_xor_sync(0xffffffffu, z2, o);
    }
    float iz1 = 1.f / z1, iz2 = 1.f / z2;

    float2* es1p = (float2*)&g_ES[((size_t)b*LV + row0 + r1)*LT] + (lane & 3);
    float2* es2p = (float2*)&g_ES[((size_t)b*LV + row0 + r2)*LT] + (lane & 3);
    #pragma unroll
    for (int nt = 0; nt < 8; nt++) {
        float es1a = acc[nt][0], es1b = acc[nt][1];   // exp(S) row1 (shift-free)
        float es2a = acc[nt][2], es2b = acc[nt][3];
        es1p[nt*4] = make_float2(es1a, es1b);
        es2p[nt*4] = make_float2(es2a, es2b);
        float a1a = es1a*iz1, a1b = es1b*iz1;          // A_vt
        float a2a = es2a*iz2, a2b = es2b*iz2;
        float w1a = __expf(a1a*0.5f), w1b = __expf(a1b*0.5f);
        float w2a = __expf(a2a*0.5f), w2b = __expf(a2b*0.5f);
        float dpa = w1a + w2a,          dpb = w1b + w2b;
        float npa = w1a*a1a + w2a*a2a,  npb = w1b*a1b + w2b*a2b;
        float zpa = es1a + es2a,        zpb = es1b + es2b;
        // reduce the 8 row-groups of the warp right away (6 live regs, not 48)
        #pragma unroll
        for (int o = 4; o <= 16; o <<= 1) {
            dpa += __shfl_xor_sync(0xffffffffu, dpa, o);
            dpb += __shfl_xor_sync(0xffffffffu, dpb, o);
            npa += __shfl_xor_sync(0xffffffffu, npa, o);
            npb += __shfl_xor_sync(0xffffffffu, npb, o);
            zpa += __shfl_xor_sync(0xffffffffu, zpa, o);
            zpb += __shfl_xor_sync(0xffffffffu, zpb, o);
        }
        if (lane < 4) {
            int col = nt*8 + lane*2;
            red[w*192 +       col] = dpa;  red[w*192 +       col+1] = dpb;
            red[w*192 +  64 + col] = npa;  red[w*192 +  64 + col+1] = npb;
            red[w*192 + 128 + col] = zpa;  red[w*192 + 128 + col+1] = zpb;
        }
    }
    __syncthreads();
    if (tid < 192) {
        float s = 0.f;
        #pragma unroll
        for (int y = 0; y < 8; y++) s += red[y*192 + tid];
        int which = tid >> 6, t = tid & 63;
        float* dst = (which == 0) ? g_den : ((which == 1) ? g_num : g_zc);
        atomicAdd(&dst[b*LT + t], s);
    }
}

// ---------------- kernel 3: text_score -> w = ts / Zc ----------------
__global__ void k3_ts() {
    int b = blockIdx.x, t = threadIdx.x;
    int i = b*LT + t;
    float ts = g_num[i] / g_den[i];
    float s = ts;
    #pragma unroll
    for (int o = 16; o >= 1; o >>= 1) s += __shfl_xor_sync(0xffffffffu, s, o);
    __shared__ float sh[2];
    if ((t & 31) == 0) sh[t >> 5] = s;
    __syncthreads();
    float tot = sh[0] + sh[1];
    ts = ts / (tot + EPSF);
    g_w[i] = ts / g_zc[i];
}

// ---------------- kernel 4: scores = ES . w, plus min/max ----------------
// 64 rows/block; thread handles one row-quarter: 16 cols = 4 back-to-back LDG.128.
__global__ __launch_bounds__(256) void k4_score(float* __restrict__ out) {
    int b   = blockIdx.y;
    int tid = threadIdx.x;
    __shared__ float w_s[LT];
    __shared__ float sc_s[64];
    if (tid < LT) w_s[tid] = g_w[b*LT + tid];
    __syncthreads();
    int r  = blockIdx.x*64 + (tid >> 2);
    int q  = tid & 3;                       // col quarter
    const float* e = g_ES + ((size_t)b*LV + r)*LT + q*16;
    float4 e0 = *(const float4*)e;
    float4 e1 = *(const float4*)(e + 4);
    float4 e2 = *(const float4*)(e + 8);
    float4 e3 = *(const float4*)(e + 12);
    const float* wq = w_s + q*16;
    float s = e0.x*wq[0]  + e0.y*wq[1]  + e0.z*wq[2]  + e0.w*wq[3]
            + e1.x*wq[4]  + e1.y*wq[5]  + e1.z*wq[6]  + e1.w*wq[7]
            + e2.x*wq[8]  + e2.y*wq[9]  + e2.z*wq[10] + e2.w*wq[11]
            + e3.x*wq[12] + e3.y*wq[13] + e3.z*wq[14] + e3.w*wq[15];
    s += __shfl_xor_sync(0xffffffffu, s, 1);
    s += __shfl_xor_sync(0xffffffffu, s, 2);
    if (q == 0) { out[(size_t)b*LV + r] = s; sc_s[tid >> 2] = s; }
    __syncthreads();
    if (tid == 0) {
        float mn = sc_s[0], mx = sc_s[0];
        #pragma unroll
        for (int i = 1; i < 64; i++) { mn = fminf(mn, sc_s[i]); mx = fmaxf(mx, sc_s[i]); }
        atomicMin(&g_mn[b], __float_as_uint(mn));   // scores > 0: uint order == float order
        atomicMax(&g_mx[b], __float_as_uint(mx));
    }
}

// ---------------- kernel 5: min-max rescale ----------------
__global__ void k5_final(float* __restrict__ out) {
    int idx = blockIdx.x*256 + threadIdx.x;
    int b = idx >> 14;
    float mn = __uint_as_float(g_mn[b]);
    float mx = __uint_as_float(g_mx[b]);
    out[idx] = (out[idx] - mn) / (mx - mn + EPSF);
}

extern "C" void kernel_launch(void* const* d_in, const int* in_sizes, int n_in,
                              void* d_out, int out_size) {
    const float* t = (const float*)d_in[0];
    const float* v = (const float*)d_in[1];
    if (in_sizes[0] != BB*LT*DD) { const float* tmp = t; t = v; v = tmp; }

    cudaFuncSetAttribute(k2_main, cudaFuncAttributeMaxDynamicSharedMemorySize, SM_TOTAL);

    k1_norm_t<<<BB*LT, 256>>>(t);
    k2_main<<<dim3(LV/128, BB), 256, SM_TOTAL>>>(v);
    k3_ts<<<BB, 64>>>();
    k4_score<<<dim3(LV/64, BB), 256>>>((float*)d_out);
    k5_final<<<(BB*LV)/256, 256>>>((float*)d_out);
}

// round 11
// speedup vs baseline: 1.0727x; 1.0727x over previous
#include <cuda_runtime.h>
#include <cuda_fp16.h>
#include <math.h>
#include <cstdint>

#define BB 8
#define LT 64
#define LV 16384
#define DD 256
#define EPSF 1e-6f

typedef unsigned int uint32;

#define PK 264   // padded row stride in fp16 elems (528B; conflict-free ldmatrix)

// smem byte offsets
#define SM_V    0                      // 128*264*2 = 67584
#define SM_T    67584                  // 64*264*2  = 33792
#define SM_RN   101376                 // 512
#define SM_RED  101888                 // 8*192*4 = 6144
#define SM_TOTAL 108032                // x2 CTAs = 216064

// ---------------- device globals ----------------
__device__ __half g_t16[BB*LT*DD];    // fp16 normalized t
__device__ float g_ES[(size_t)BB*LV*LT];
__device__ float g_den[BB*LT];
__device__ float g_num[BB*LT];
__device__ float g_zc[BB*LT];
__device__ unsigned g_mn[BB];
__device__ unsigned g_mx[BB];

__device__ __forceinline__ float fixf(float x) {
    if (isnan(x)) return 0.f;
    return fminf(fmaxf(x, -3.402823466e38f), 3.402823466e38f);
}
__device__ __forceinline__ uint32 smem_u32(const void* p) {
    uint32 a;
    asm("{ .reg .u64 t; cvta.to.shared.u64 t, %1; cvt.u32.u64 %0, t; }" : "=r"(a) : "l"(p));
    return a;
}
__device__ __forceinline__ uint32 packh2(float a, float b) {
    __half2 h = __floats2half2_rn(a, b);
    return *(uint32*)&h;
}

#define LDMX4(r, addr) \
    asm volatile("ldmatrix.sync.aligned.m8n8.x4.shared.b16 {%0,%1,%2,%3}, [%4];" \
        : "=r"((r)[0]), "=r"((r)[1]), "=r"((r)[2]), "=r"((r)[3]) : "r"(addr))

#define MMAH(c, a, b0, b1) \
    asm volatile("mma.sync.aligned.m16n8k16.row.col.f32.f16.f16.f32 " \
        "{%0,%1,%2,%3},{%4,%5,%6,%7},{%8,%9},{%0,%1,%2,%3};" \
        : "+f"((c)[0]), "+f"((c)[1]), "+f"((c)[2]), "+f"((c)[3]) \
        : "r"((a)[0]), "r"((a)[1]), "r"((a)[2]), "r"((a)[3]), "r"(b0), "r"(b1))

// ---------------- kernel 1: normalize t -> fp16; init accumulators ----------------
__global__ void k1_norm_t(const float* __restrict__ t) {
    int row = blockIdx.x;         // 0..511
    int tid = threadIdx.x;        // 0..255 = k
    if (row == 0) {
        for (int j = tid; j < BB*LT; j += 256) {
            g_den[j] = 0.f; g_num[j] = 0.f; g_zc[j] = 0.f;
        }
        if (tid < BB) { g_mn[tid] = 0x7F800000u; g_mx[tid] = 0u; }
    }
    float x = fixf(t[row*DD + tid]);
    float ss = x * x;
    #pragma unroll
    for (int o = 16; o >= 1; o >>= 1) ss += __shfl_xor_sync(0xffffffffu, ss, o);
    __shared__ float sh[8];
    if ((tid & 31) == 0) sh[tid >> 5] = ss;
    __syncthreads();
    float tot = 0.f;
    #pragma unroll
    for (int w = 0; w < 8; w++) tot += sh[w];
    float xn = x / fmaxf(sqrtf(tot), EPSF);
    g_t16[row*DD + tid] = __float2half_rn(xn);
}

// ---------------- kernel 2: single-pass fp16 HMMA S-GEMM + fused softmaxes ----------------
__global__ __launch_bounds__(256, 2) void k2_main(const float* __restrict__ v) {
    extern __shared__ char smc[];
    uint32 smb = smem_u32(smc);
    int b    = blockIdx.y;
    int row0 = blockIdx.x * 128;
    int tid  = threadIdx.x;
    int lane = tid & 31, w = tid >> 5;
    float* rn_s = (float*)(smc + SM_RN);
    float* red  = (float*)(smc + SM_RED);

    // ---- prologue: T fp16 tile into padded smem ----
    {
        const uint4* t4 = (const uint4*)(g_t16 + b*LT*DD);
        #pragma unroll
        for (int it = 0; it < 8; it++) {
            int i = tid + it*256;
            int r = i >> 5, c = i & 31;
            *(uint4*)(smc + SM_T + (uint32)(r*PK + c*8)*2) = t4[i];
        }
    }
    // ---- prologue: V -> fp16 + row norms (streaming loads: v is read once) ----
    {
        int vrow = tid >> 1, khalf = (tid & 1) * 128;
        const float4* vr = (const float4*)(v + ((size_t)b*LV + row0 + vrow)*DD + khalf);
        float ss = 0.f;
        #pragma unroll 4
        for (int c = 0; c < 16; c++) {
            float4 p0 = __ldcs(vr + 2*c);
            float4 p1 = __ldcs(vr + 2*c + 1);
            float x0=fixf(p0.x), x1=fixf(p0.y), x2=fixf(p0.z), x3=fixf(p0.w);
            float x4=fixf(p1.x), x5=fixf(p1.y), x6=fixf(p1.z), x7=fixf(p1.w);
            ss += x0*x0 + x1*x1 + x2*x2 + x3*x3 + x4*x4 + x5*x5 + x6*x6 + x7*x7;
            uint4 st = make_uint4(packh2(x0,x1), packh2(x2,x3), packh2(x4,x5), packh2(x6,x7));
            *(uint4*)(smc + SM_V + (uint32)(vrow*PK + khalf + c*8)*2) = st;
        }
        float st = ss + __shfl_xor_sync(0xffffffffu, ss, 1);
        if ((tid & 1) == 0) rn_s[vrow] = 0.5f / fmaxf(sqrtf(st), EPSF);
    }
    __syncthreads();

    // ---- mainloop: 16 k-steps; batch all 5 LDSMs per step, then 8 MMAs ----
    float acc[8][4];
    #pragma unroll
    for (int nt = 0; nt < 8; nt++)
        #pragma unroll
        for (int j = 0; j < 4; j++) acc[nt][j] = 0.f;

    uint32 a_row = 16*w + (lane & 15);
    uint32 a_k8  = (lane >> 4) * 8;
    uint32 a_addr = smb + SM_V + (a_row*PK + a_k8) * 2;
    uint32 b_row = (lane & 7) + ((lane >> 4) << 3);
    uint32 b_k8  = ((lane >> 3) & 1) * 8;
    uint32 b_base = smb + SM_T + (b_row*PK + b_k8) * 2;

    #pragma unroll 4
    for (int ks = 0; ks < 16; ks++) {
        uint32 a[4], bh[4][4];
        LDMX4(a, a_addr + ks*32);
        LDMX4(bh[0], b_base +               ks*32);
        LDMX4(bh[1], b_base + 1*(16*PK*2) + ks*32);
        LDMX4(bh[2], b_base + 2*(16*PK*2) + ks*32);
        LDMX4(bh[3], b_base + 3*(16*PK*2) + ks*32);
        #pragma unroll
        for (int nc = 0; nc < 4; nc++) {
            MMAH(acc[2*nc],   a, bh[nc][0], bh[nc][1]);
            MMAH(acc[2*nc+1], a, bh[nc][2], bh[nc][3]);
        }
    }

    // ---- epilogue: shift-free softmax over t (|S|<=0.5), ES store, accumulators ----
    int r1 = 16*w + (lane >> 2);
    int r2 = r1 + 8;
    float sc1 = rn_s[r1], sc2 = rn_s[r2];

    float z1 = 0.f, z2 = 0.f;
    #pragma unroll
    for (int nt = 0; nt < 8; nt++) {
        acc[nt][0] = __expf(acc[nt][0]*sc1); z1 += acc[nt][0];
        acc[nt][1] = __expf(acc[nt][1]*sc1); z1 += acc[nt][1];
        acc[nt][2] = __expf(acc[nt][2]*sc2); z2 += acc[nt][2];
        acc[nt][3] = __expf(acc[nt][3]*sc2); z2 += acc[nt][3];
    }
    #pragma unroll
    for (int o = 1; o < 4; o <<= 1) {
        z1 += __shfl_xor_sync(0xffffffffu, z1, o);
        z2 += __shfl_xor_sync(0xffffffffu, z2, o);
    }
    float iz1 = 1.f / z1, iz2 = 1.f / z2;

    float2* es1p = (float2*)&g_ES[((size_t)b*LV + row0 + r1)*LT] + (lane & 3);
    float2* es2p = (float2*)&g_ES[((size_t)b*LV + row0 + r2)*LT] + (lane & 3);
    #pragma unroll
    for (int nt = 0; nt < 8; nt++) {
        float es1a = acc[nt][0], es1b = acc[nt][1];
        float es2a = acc[nt][2], es2b = acc[nt][3];
        es1p[nt*4] = make_float2(es1a, es1b);
        es2p[nt*4] = make_float2(es2a, es2b);
        float a1a = es1a*iz1, a1b = es1b*iz1;
        float a2a = es2a*iz2, a2b = es2b*iz2;
        float w1a = __expf(a1a*0.5f), w1b = __expf(a1b*0.5f);
        float w2a = __expf(a2a*0.5f), w2b = __expf(a2b*0.5f);
        float dpa = w1a + w2a,          dpb = w1b + w2b;
        float npa = w1a*a1a + w2a*a2a,  npb = w1b*a1b + w2b*a2b;
        float zpa = es1a + es2a,        zpb = es1b + es2b;
        #pragma unroll
        for (int o = 4; o <= 16; o <<= 1) {
            dpa += __shfl_xor_sync(0xffffffffu, dpa, o);
            dpb += __shfl_xor_sync(0xffffffffu, dpb, o);
            npa += __shfl_xor_sync(0xffffffffu, npa, o);
            npb += __shfl_xor_sync(0xffffffffu, npb, o);
            zpa += __shfl_xor_sync(0xffffffffu, zpa, o);
            zpb += __shfl_xor_sync(0xffffffffu, zpb, o);
        }
        if (lane < 4) {
            int col = nt*8 + lane*2;
            red[w*192 +       col] = dpa;  red[w*192 +       col+1] = dpb;
            red[w*192 +  64 + col] = npa;  red[w*192 +  64 + col+1] = npb;
            red[w*192 + 128 + col] = zpa;  red[w*192 + 128 + col+1] = zpb;
        }
    }
    __syncthreads();
    if (tid < 192) {
        float s = 0.f;
        #pragma unroll
        for (int y = 0; y < 8; y++) s += red[y*192 + tid];
        int which = tid >> 6, t = tid & 63;
        float* dst = (which == 0) ? g_den : ((which == 1) ? g_num : g_zc);
        atomicAdd(&dst[b*LT + t], s);
    }
}

// ---------------- kernel 4: w recomputed per block; scores = ES . w; min/max ----------------
__global__ __launch_bounds__(256) void k4_score(float* __restrict__ out) {
    int b   = blockIdx.y;
    int tid = threadIdx.x;
    __shared__ float w_s[LT];
    __shared__ float sc_s[64];
    __shared__ float tsum[2];
    // fused k3: text_score -> w (recomputed cheaply per block; inputs L2-hot)
    if (tid < LT) {
        float ts = g_num[b*LT + tid] / g_den[b*LT + tid];
        w_s[tid] = ts;
        float s = ts;
        #pragma unroll
        for (int o = 16; o >= 1; o >>= 1) s += __shfl_xor_sync(0xffffffffu, s, o);
        if ((tid & 31) == 0) tsum[tid >> 5] = s;
    }
    __syncthreads();
    if (tid < LT) {
        float tot = tsum[0] + tsum[1];
        w_s[tid] = w_s[tid] / (tot + EPSF) / g_zc[b*LT + tid];
    }
    __syncthreads();

    int r = blockIdx.x*64 + (tid >> 2);
    int q = tid & 3;
    const float* e = g_ES + ((size_t)b*LV + r)*LT + q*16;
    float4 e0 = *(const float4*)e;
    float4 e1 = *(const float4*)(e + 4);
    float4 e2 = *(const float4*)(e + 8);
    float4 e3 = *(const float4*)(e + 12);
    const float* wq = w_s + q*16;
    float s = e0.x*wq[0]  + e0.y*wq[1]  + e0.z*wq[2]  + e0.w*wq[3]
            + e1.x*wq[4]  + e1.y*wq[5]  + e1.z*wq[6]  + e1.w*wq[7]
            + e2.x*wq[8]  + e2.y*wq[9]  + e2.z*wq[10] + e2.w*wq[11]
            + e3.x*wq[12] + e3.y*wq[13] + e3.z*wq[14] + e3.w*wq[15];
    s += __shfl_xor_sync(0xffffffffu, s, 1);
    s += __shfl_xor_sync(0xffffffffu, s, 2);
    if (q == 0) { out[(size_t)b*LV + r] = s; sc_s[tid >> 2] = s; }
    __syncthreads();
    // warp-parallel min/max over the 64 row scores
    if (tid < 64) {
        float x = sc_s[tid];
        float mn = x, mx = x;
        #pragma unroll
        for (int o = 16; o >= 1; o >>= 1) {
            mn = fminf(mn, __shfl_xor_sync(0xffffffffu, mn, o));
            mx = fmaxf(mx, __shfl_xor_sync(0xffffffffu, mx, o));
        }
        if ((tid & 31) == 0) {
            atomicMin(&g_mn[b], __float_as_uint(mn));   // scores > 0: uint order == float order
            atomicMax(&g_mx[b], __float_as_uint(mx));
        }
    }
}

// ---------------- kernel 5: min-max rescale ----------------
__global__ void k5_final(float* __restrict__ out) {
    int idx = blockIdx.x*256 + threadIdx.x;
    int b = idx >> 14;
    float mn = __uint_as_float(g_mn[b]);
    float mx = __uint_as_float(g_mx[b]);
    out[idx] = (out[idx] - mn) / (mx - mn + EPSF);
}

extern "C" void kernel_launch(void* const* d_in, const int* in_sizes, int n_in,
                              void* d_out, int out_size) {
    const float* t = (const float*)d_in[0];
    const float* v = (const float*)d_in[1];
    if (in_sizes[0] != BB*LT*DD) { const float* tmp = t; t = v; v = tmp; }

    cudaFuncSetAttribute(k2_main, cudaFuncAttributeMaxDynamicSharedMemorySize, SM_TOTAL);

    k1_norm_t<<<BB*LT, 256>>>(t);
    k2_main<<<dim3(LV/128, BB), 256, SM_TOTAL>>>(v);
    k4_score<<<dim3(LV/64, BB), 256>>>((float*)d_out);
    k5_final<<<(BB*LV)/256, 256>>>((float*)d_out);
}

// round 12
// speedup vs baseline: 1.3078x; 1.2191x over previous
#include <cuda_runtime.h>
#include <cuda_fp16.h>
#include <math.h>
#include <cstdint>

#define BB 8
#define LT 64
#define LV 16384
#define DD 256
#define EPSF 1e-6f

typedef unsigned int uint32;

#define PK 264   // padded row stride in fp16 elems (528B; conflict-free ldmatrix)

// smem byte offsets
#define SM_V    0                      // 128*264*2 = 67584
#define SM_T    67584                  // 64*264*2  = 33792
#define SM_RN   101376                 // 512
#define SM_RED  101888                 // 8*192*4 = 6144
#define SM_TOTAL 108032                // x2 CTAs = 216064

// ---------------- device globals ----------------
__device__ __half g_t16[BB*LT*DD];    // fp16 normalized t
__device__ float g_ES[(size_t)BB*LV*LT];
__device__ float g_den[BB*LT];
__device__ float g_num[BB*LT];
__device__ float g_zc[BB*LT];
__device__ unsigned g_mn[BB];
__device__ unsigned g_mx[BB];

__device__ __forceinline__ float fixf(float x) {
    if (isnan(x)) return 0.f;
    return fminf(fmaxf(x, -3.402823466e38f), 3.402823466e38f);
}
__device__ __forceinline__ uint32 smem_u32(const void* p) {
    uint32 a;
    asm("{ .reg .u64 t; cvta.to.shared.u64 t, %1; cvt.u32.u64 %0, t; }" : "=r"(a) : "l"(p));
    return a;
}
__device__ __forceinline__ uint32 packh2(float a, float b) {
    __half2 h = __floats2half2_rn(a, b);
    return *(uint32*)&h;
}

#define LDMX4(r, addr) \
    asm volatile("ldmatrix.sync.aligned.m8n8.x4.shared.b16 {%0,%1,%2,%3}, [%4];" \
        : "=r"((r)[0]), "=r"((r)[1]), "=r"((r)[2]), "=r"((r)[3]) : "r"(addr))

#define MMAH(c, a, b0, b1) \
    asm volatile("mma.sync.aligned.m16n8k16.row.col.f32.f16.f16.f32 " \
        "{%0,%1,%2,%3},{%4,%5,%6,%7},{%8,%9},{%0,%1,%2,%3};" \
        : "+f"((c)[0]), "+f"((c)[1]), "+f"((c)[2]), "+f"((c)[3]) \
        : "r"((a)[0]), "r"((a)[1]), "r"((a)[2]), "r"((a)[3]), "r"(b0), "r"(b1))

// ---------------- kernel 1: normalize t -> fp16; init accumulators ----------------
__global__ void k1_norm_t(const float* __restrict__ t) {
    int row = blockIdx.x;         // 0..511
    int tid = threadIdx.x;        // 0..255 = k
    if (row == 0) {
        for (int j = tid; j < BB*LT; j += 256) {
            g_den[j] = 0.f; g_num[j] = 0.f; g_zc[j] = 0.f;
        }
        if (tid < BB) { g_mn[tid] = 0x7F800000u; g_mx[tid] = 0u; }
    }
    float x = fixf(t[row*DD + tid]);
    float ss = x * x;
    #pragma unroll
    for (int o = 16; o >= 1; o >>= 1) ss += __shfl_xor_sync(0xffffffffu, ss, o);
    __shared__ float sh[8];
    if ((tid & 31) == 0) sh[tid >> 5] = ss;
    __syncthreads();
    float tot = 0.f;
    #pragma unroll
    for (int w = 0; w < 8; w++) tot += sh[w];
    float xn = x / fmaxf(sqrtf(tot), EPSF);
    g_t16[row*DD + tid] = __float2half_rn(xn);
}

// ---------------- kernel 2: single-pass fp16 HMMA S-GEMM + fused softmaxes ----------------
__global__ __launch_bounds__(256, 2) void k2_main(const float* __restrict__ v) {
    extern __shared__ char smc[];
    uint32 smb = smem_u32(smc);
    int b    = blockIdx.y;
    int row0 = blockIdx.x * 128;
    int tid  = threadIdx.x;
    int lane = tid & 31, w = tid >> 5;
    float* rn_s = (float*)(smc + SM_RN);
    float* red  = (float*)(smc + SM_RED);

    // ---- prologue: T fp16 tile into padded smem (coalesced) ----
    {
        const uint4* t4 = (const uint4*)(g_t16 + b*LT*DD);
        #pragma unroll
        for (int it = 0; it < 8; it++) {
            int i = tid + it*256;
            int r = i >> 5, c = i & 31;
            *(uint4*)(smc + SM_T + (uint32)(r*PK + c*8)*2) = t4[i];
        }
    }
    // ---- prologue: V -> fp16, FULLY COALESCED (consecutive lanes = consecutive float4) ----
    {
        const float4* vb = (const float4*)(v + ((size_t)b*LV + row0)*DD);
        #pragma unroll 8
        for (int it = 0; it < 32; it++) {
            int idx = it*256 + tid;          // 0..8191, contiguous across block
            int row = idx >> 6, j = idx & 63;
            float4 p = __ldcs(vb + idx);
            float x0=fixf(p.x), x1=fixf(p.y), x2=fixf(p.z), x3=fixf(p.w);
            *(uint2*)(smc + SM_V + (uint32)(row*PK + j*4)*2)
                = make_uint2(packh2(x0,x1), packh2(x2,x3));
        }
    }
    __syncthreads();
    // ---- row norms from the fp16 tile (cheap LDS pass) ----
    {
        int vrow = tid >> 1, kh = (tid & 1) * 128;
        const uint4* hp = (const uint4*)(smc + SM_V + (uint32)(vrow*PK + kh)*2);
        float ss = 0.f;
        #pragma unroll
        for (int c = 0; c < 16; c++) {
            uint4 u = hp[c];
            float2 f0 = __half22float2(*(__half2*)&u.x);
            float2 f1 = __half22float2(*(__half2*)&u.y);
            float2 f2 = __half22float2(*(__half2*)&u.z);
            float2 f3 = __half22float2(*(__half2*)&u.w);
            ss += f0.x*f0.x + f0.y*f0.y + f1.x*f1.x + f1.y*f1.y
                + f2.x*f2.x + f2.y*f2.y + f3.x*f3.x + f3.y*f3.y;
        }
        float st = ss + __shfl_xor_sync(0xffffffffu, ss, 1);
        if ((tid & 1) == 0) rn_s[vrow] = 0.5f / fmaxf(sqrtf(st), EPSF);
    }
    __syncthreads();

    // ---- mainloop: 16 k-steps; batch all 5 LDSMs per step, then 8 MMAs ----
    float acc[8][4];
    #pragma unroll
    for (int nt = 0; nt < 8; nt++)
        #pragma unroll
        for (int j = 0; j < 4; j++) acc[nt][j] = 0.f;

    uint32 a_row = 16*w + (lane & 15);
    uint32 a_k8  = (lane >> 4) * 8;
    uint32 a_addr = smb + SM_V + (a_row*PK + a_k8) * 2;
    uint32 b_row = (lane & 7) + ((lane >> 4) << 3);
    uint32 b_k8  = ((lane >> 3) & 1) * 8;
    uint32 b_base = smb + SM_T + (b_row*PK + b_k8) * 2;

    #pragma unroll 4
    for (int ks = 0; ks < 16; ks++) {
        uint32 a[4], bh[4][4];
        LDMX4(a, a_addr + ks*32);
        LDMX4(bh[0], b_base +               ks*32);
        LDMX4(bh[1], b_base + 1*(16*PK*2) + ks*32);
        LDMX4(bh[2], b_base + 2*(16*PK*2) + ks*32);
        LDMX4(bh[3], b_base + 3*(16*PK*2) + ks*32);
        #pragma unroll
        for (int nc = 0; nc < 4; nc++) {
            MMAH(acc[2*nc],   a, bh[nc][0], bh[nc][1]);
            MMAH(acc[2*nc+1], a, bh[nc][2], bh[nc][3]);
        }
    }

    // ---- epilogue: shift-free softmax over t (|S|<=0.5), ES store, accumulators ----
    int r1 = 16*w + (lane >> 2);
    int r2 = r1 + 8;
    float sc1 = rn_s[r1], sc2 = rn_s[r2];

    float z1 = 0.f, z2 = 0.f;
    #pragma unroll
    for (int nt = 0; nt < 8; nt++) {
        acc[nt][0] = __expf(acc[nt][0]*sc1); z1 += acc[nt][0];
        acc[nt][1] = __expf(acc[nt][1]*sc1); z1 += acc[nt][1];
        acc[nt][2] = __expf(acc[nt][2]*sc2); z2 += acc[nt][2];
        acc[nt][3] = __expf(acc[nt][3]*sc2); z2 += acc[nt][3];
    }
    #pragma unroll
    for (int o = 1; o < 4; o <<= 1) {
        z1 += __shfl_xor_sync(0xffffffffu, z1, o);
        z2 += __shfl_xor_sync(0xffffffffu, z2, o);
    }
    float iz1 = 1.f / z1, iz2 = 1.f / z2;

    float2* es1p = (float2*)&g_ES[((size_t)b*LV + row0 + r1)*LT] + (lane & 3);
    float2* es2p = (float2*)&g_ES[((size_t)b*LV + row0 + r2)*LT] + (lane & 3);
    #pragma unroll
    for (int nt = 0; nt < 8; nt++) {
        float es1a = acc[nt][0], es1b = acc[nt][1];
        float es2a = acc[nt][2], es2b = acc[nt][3];
        es1p[nt*4] = make_float2(es1a, es1b);
        es2p[nt*4] = make_float2(es2a, es2b);
        float a1a = es1a*iz1, a1b = es1b*iz1;
        float a2a = es2a*iz2, a2b = es2b*iz2;
        float w1a = __expf(a1a*0.5f), w1b = __expf(a1b*0.5f);
        float w2a = __expf(a2a*0.5f), w2b = __expf(a2b*0.5f);
        float dpa = w1a + w2a,          dpb = w1b + w2b;
        float npa = w1a*a1a + w2a*a2a,  npb = w1b*a1b + w2b*a2b;
        float zpa = es1a + es2a,        zpb = es1b + es2b;
        #pragma unroll
        for (int o = 4; o <= 16; o <<= 1) {
            dpa += __shfl_xor_sync(0xffffffffu, dpa, o);
            dpb += __shfl_xor_sync(0xffffffffu, dpb, o);
            npa += __shfl_xor_sync(0xffffffffu, npa, o);
            npb += __shfl_xor_sync(0xffffffffu, npb, o);
            zpa += __shfl_xor_sync(0xffffffffu, zpa, o);
            zpb += __shfl_xor_sync(0xffffffffu, zpb, o);
        }
        if (lane < 4) {
            int col = nt*8 + lane*2;
            red[w*192 +       col] = dpa;  red[w*192 +       col+1] = dpb;
            red[w*192 +  64 + col] = npa;  red[w*192 +  64 + col+1] = npb;
            red[w*192 + 128 + col] = zpa;  red[w*192 + 128 + col+1] = zpb;
        }
    }
    __syncthreads();
    if (tid < 192) {
        float s = 0.f;
        #pragma unroll
        for (int y = 0; y < 8; y++) s += red[y*192 + tid];
        int which = tid >> 6, t = tid & 63;
        float* dst = (which == 0) ? g_den : ((which == 1) ? g_num : g_zc);
        atomicAdd(&dst[b*LT + t], s);
    }
}

// ---------------- kernel 4: w recomputed per block; scores = ES . w; min/max ----------------
// Warp reads 2 full ES rows per LDG.128 request (16 lanes x 16B = 256B row): nL=2, MLP=4.
__global__ __launch_bounds__(256) void k4_score(float* __restrict__ out) {
    int b   = blockIdx.y;
    int tid = threadIdx.x;
    __shared__ float w_s[LT];
    __shared__ float sc_s[64];
    __shared__ float tsum[2];
    // fused k3: text_score -> w
    if (tid < LT) {
        float ts = g_num[b*LT + tid] / g_den[b*LT + tid];
        w_s[tid] = ts;
        float s = ts;
        #pragma unroll
        for (int o = 16; o >= 1; o >>= 1) s += __shfl_xor_sync(0xffffffffu, s, o);
        if ((tid & 31) == 0) tsum[tid >> 5] = s;
    }
    __syncthreads();
    if (tid < LT) {
        float tot = tsum[0] + tsum[1];
        w_s[tid] = w_s[tid] / (tot + EPSF) / g_zc[b*LT + tid];
    }
    __syncthreads();

    int lane = tid & 31, wp = tid >> 5;
    int r0 = blockIdx.x*64 + wp*8;               // warp owns 8 rows
    const float4* ep = (const float4*)(g_ES + ((size_t)b*LV + r0)*LT) + lane;
    float4 e0 = ep[0], e1 = ep[32], e2 = ep[64], e3 = ep[96];   // 4 independent coalesced loads
    float4 wv = *(float4*)&w_s[(lane & 15)*4];
    float p0 = e0.x*wv.x + e0.y*wv.y + e0.z*wv.z + e0.w*wv.w;
    float p1 = e1.x*wv.x + e1.y*wv.y + e1.z*wv.z + e1.w*wv.w;
    float p2 = e2.x*wv.x + e2.y*wv.y + e2.z*wv.z + e2.w*wv.w;
    float p3 = e3.x*wv.x + e3.y*wv.y + e3.z*wv.z + e3.w*wv.w;
    #pragma unroll
    for (int o = 1; o <= 8; o <<= 1) {
        p0 += __shfl_xor_sync(0xffffffffu, p0, o);
        p1 += __shfl_xor_sync(0xffffffffu, p1, o);
        p2 += __shfl_xor_sync(0xffffffffu, p2, o);
        p3 += __shfl_xor_sync(0xffffffffu, p3, o);
    }
    if ((lane & 15) == 0) {
        int h = lane >> 4;                        // 0 or 1
        size_t base = (size_t)b*LV + r0 + h;
        out[base + 0] = p0; sc_s[wp*8 + h + 0] = p0;
        out[base + 2] = p1; sc_s[wp*8 + h + 2] = p1;
        out[base + 4] = p2; sc_s[wp*8 + h + 4] = p2;
        out[base + 6] = p3; sc_s[wp*8 + h + 6] = p3;
    }
    __syncthreads();
    if (tid < 64) {
        float x = sc_s[tid];
        float mn = x, mx = x;
        #pragma unroll
        for (int o = 16; o >= 1; o >>= 1) {
            mn = fminf(mn, __shfl_xor_sync(0xffffffffu, mn, o));
            mx = fmaxf(mx, __shfl_xor_sync(0xffffffffu, mx, o));
        }
        if ((tid & 31) == 0) {
            atomicMin(&g_mn[b], __float_as_uint(mn));   // scores > 0: uint order == float order
            atomicMax(&g_mx[b], __float_as_uint(mx));
        }
    }
}

// ---------------- kernel 5: min-max rescale (float4, reciprocal) ----------------
__global__ void k5_final(float4* __restrict__ out4) {
    int i = blockIdx.x*256 + threadIdx.x;   // 0..32767 float4s
    int b = i >> 12;                        // 4096 float4 per batch
    float mn = __uint_as_float(g_mn[b]);
    float mx = __uint_as_float(g_mx[b]);
    float inv = 1.f / (mx - mn + EPSF);
    float4 o = out4[i];
    o.x = (o.x - mn) * inv;
    o.y = (o.y - mn) * inv;
    o.z = (o.z - mn) * inv;
    o.w = (o.w - mn) * inv;
    out4[i] = o;
}

extern "C" void kernel_launch(void* const* d_in, const int* in_sizes, int n_in,
                              void* d_out, int out_size) {
    const float* t = (const float*)d_in[0];
    const float* v = (const float*)d_in[1];
    if (in_sizes[0] != BB*LT*DD) { const float* tmp = t; t = v; v = tmp; }

    cudaFuncSetAttribute(k2_main, cudaFuncAttributeMaxDynamicSharedMemorySize, SM_TOTAL);

    k1_norm_t<<<BB*LT, 256>>>(t);
    k2_main<<<dim3(LV/128, BB), 256, SM_TOTAL>>>(v);
    k4_score<<<dim3(LV/64, BB), 256>>>((float*)d_out);
    k5_final<<<(BB*LV/4)/256, 256>>>((float4*)d_out);
}